// round 17
// baseline (speedup 1.0000x reference)
#include <cuda_runtime.h>
#include <cstddef>

#define BB 4
#define LL 2048
#define HH 8
#define DD 64
#define SK 40
#define NT 40
#define BHN 32
#define NSPLIT 16
#define CHUNK 128
#define KTPAD 132
#define SCALE 0.125f

#define NSAMPBLK (BHN * LL / 32)  // 2048 sample blocks (4 l's per warp)
#define NATTNBLK (BHN * NSPLIT)   // 512 attn blocks

// ---------------- scratch ----------------
__device__ float g_M[BHN * LL];
__device__ int   g_top[BHN * NT];
__device__ float g_pm[BHN * NSPLIT * NT];
__device__ float g_pl[BHN * NSPLIT * NT];
__device__ float g_po[BHN * NSPLIT * NT * DD];
__device__ int   g_cnt1[BHN];     // zero-init; self-resetting
__device__ int   g_cnt2[BHN];     // zero-init; self-resetting
__device__ int   g_topdone[BHN];  // zero-init; self-resetting

// ---------------- packed f32x2 helpers ----------------
__device__ __forceinline__ unsigned long long pk2(float x, float y) {
    unsigned long long r;
    asm("mov.b64 %0, {%1, %2};" : "=l"(r) : "f"(x), "f"(y));
    return r;
}
__device__ __forceinline__ void upk2(unsigned long long v, float& x, float& y) {
    asm("mov.b64 {%0, %1}, %2;" : "=f"(x), "=f"(y) : "l"(v));
}
__device__ __forceinline__ unsigned long long ffma2(unsigned long long a,
                                                    unsigned long long b,
                                                    unsigned long long c) {
    unsigned long long d;
    asm("fma.rn.f32x2 %0, %1, %2, %3;" : "=l"(d) : "l"(a), "l"(b), "l"(c));
    return d;
}

// ================= fused kernel =================
__global__ void __launch_bounds__(256, 2)
fused_kernel(const float* __restrict__ Q,
             const float* __restrict__ K,
             const float* __restrict__ V,
             const void*  __restrict__ idxbuf,
             float* __restrict__ out) {
    extern __shared__ float smem[];
    __shared__ int s_last;

    if (blockIdx.x < NSAMPBLK) {
        // ======================= SAMPLE ROLE: 4 l's per warp =======================
        int wid  = (blockIdx.x * blockDim.x + threadIdx.x) >> 5;   // 0 .. BHN*LL/4-1
        int lane = threadIdx.x & 31;
        int lp = wid % (LL / 4);
        int bh = wid / (LL / 4);
        int l0 = lp * 4;
        int b = bh >> 3, h = bh & 7;
        int g  = lane >> 3;
        int li = lane & 7;

        {
            long long v = ((const long long*)idxbuf)[lane];
            int ok = (v >= 0 && v < LL);
            unsigned mm = __ballot_sync(0xffffffffu, ok);
            int is64 = (mm == 0xffffffffu);

            int ia[4], ib[4];
#pragma unroll
            for (int q = 0; q < 4; q++) ib[q] = 0;
            if (is64) {
#pragma unroll
                for (int q = 0; q < 4; q++) {
                    const long long* p = (const long long*)idxbuf + (long long)(l0 + q) * SK;
                    ia[q] = (int)p[lane];
                    if (lane < SK - 32) ib[q] = (int)p[32 + lane];
                }
            } else {
#pragma unroll
                for (int q = 0; q < 4; q++) {
                    const int* p = (const int*)idxbuf + (l0 + q) * SK;
                    ia[q] = p[lane];
                    if (lane < SK - 32) ib[q] = p[32 + lane];
                }
            }

            float4 qa[4], qb[4];
#pragma unroll
            for (int q = 0; q < 4; q++) {
                const float* qbase = Q + (((size_t)(b * LL + l0 + q) * HH + h) << 6) + (li << 3);
                qa[q] = ((const float4*)qbase)[0];
                qb[q] = ((const float4*)qbase)[1];
            }

            const size_t kstride_h = ((size_t)h << 6) + ((size_t)li << 3);
            const float* Kb = K + ((size_t)b * LL * HH << 6);

            float mx[4], sm[4];
#pragma unroll
            for (int q = 0; q < 4; q++) { mx[q] = -3e38f; sm[q] = 0.0f; }

#pragma unroll
            for (int r = 0; r < 10; r++) {
                int s = 4 * r + g;
                float4 k0[4], k1[4];
#pragma unroll
                for (int q = 0; q < 4; q++) {
                    int j = (s < 32) ? __shfl_sync(0xffffffffu, ia[q], s)
                                     : __shfl_sync(0xffffffffu, ib[q], s - 32);
                    const float4* kp = (const float4*)(Kb + (((size_t)j * HH) << 6) + kstride_h);
                    k0[q] = kp[0];
                    k1[q] = kp[1];
                }
                float p[4];
#pragma unroll
                for (int q = 0; q < 4; q++) {
                    float pv = qa[q].x * k0[q].x;
                    pv = fmaf(qa[q].y, k0[q].y, pv);
                    pv = fmaf(qa[q].z, k0[q].z, pv);
                    pv = fmaf(qa[q].w, k0[q].w, pv);
                    pv = fmaf(qb[q].x, k1[q].x, pv);
                    pv = fmaf(qb[q].y, k1[q].y, pv);
                    pv = fmaf(qb[q].z, k1[q].z, pv);
                    pv = fmaf(qb[q].w, k1[q].w, pv);
                    p[q] = pv;
                }
#pragma unroll
                for (int q = 0; q < 4; q++) p[q] += __shfl_xor_sync(0xffffffffu, p[q], 1);
#pragma unroll
                for (int q = 0; q < 4; q++) p[q] += __shfl_xor_sync(0xffffffffu, p[q], 2);
#pragma unroll
                for (int q = 0; q < 4; q++) p[q] += __shfl_xor_sync(0xffffffffu, p[q], 4);
#pragma unroll
                for (int q = 0; q < 4; q++) {
                    mx[q] = fmaxf(mx[q], p[q]);
                    sm[q] += p[q];
                }
            }
#pragma unroll
            for (int q = 0; q < 4; q++) {
                mx[q] = fmaxf(mx[q], __shfl_xor_sync(0xffffffffu, mx[q], 8));
                mx[q] = fmaxf(mx[q], __shfl_xor_sync(0xffffffffu, mx[q], 16));
                sm[q] += __shfl_xor_sync(0xffffffffu, sm[q], 8);
                sm[q] += __shfl_xor_sync(0xffffffffu, sm[q], 16);
            }
            if (lane == 0) {
#pragma unroll
                for (int q = 0; q < 4; q++)
                    g_M[bh * LL + l0 + q] = mx[q] - sm[q] * (1.0f / (float)LL);
            }
        }

        __syncthreads();
        __threadfence();
        if (threadIdx.x == 0)
            s_last = (atomicAdd(&g_cnt1[bh], 1) == 63) ? 1 : 0;   // 64 blocks per bh
        __syncthreads();
        if (!s_last) return;

        int lane2 = threadIdx.x & 31;
        if (threadIdx.x < 32) {
            float* sM = smem;   // dynamic smem, 2048 floats
            for (int i = lane2; i < LL; i += 32) sM[i] = g_M[bh * LL + i];
            __syncwarp();

            int base = lane2 << 6;
            unsigned long long s0 = 0ull, s1 = 0ull, s2 = 0ull;
#pragma unroll 4
            for (int i = 0; i < 64; i++) {
                float x = sM[base + i];
                unsigned uv = __float_as_uint(x);
                uv ^= (uv >> 31) ? 0xffffffffu : 0x80000000u;
                unsigned long long k = ((unsigned long long)uv << 32)
                                     | (unsigned)(LL - 1 - (base + i));
                if (k > s0)      { s2 = s1; s1 = s0; s0 = k; }
                else if (k > s1) { s2 = s1; s1 = k; }
                else if (k > s2) { s2 = k; }
            }
            for (int it = 0; it < NT; it++) {
                unsigned ord0 = (unsigned)(s0 >> 32);
                unsigned m1 = __reduce_max_sync(0xffffffffu, ord0);
                unsigned lowp = (ord0 == m1) ? ((unsigned)s0 + 1u) : 0u;
                unsigned m2 = __reduce_max_sync(0xffffffffu, lowp);
                int wi = LL - (int)m2;
                if (lane2 == 0) g_top[bh * NT + it] = wi;
                if (lane2 == (wi >> 6)) {
                    sM[wi] = -3e38f;
                    s0 = s1; s1 = s2; s2 = 0ull;
                    if (s0 == 0ull) {
                        for (int i = 0; i < 64; i++) {
                            float x = sM[base + i];
                            unsigned uv = __float_as_uint(x);
                            uv ^= (uv >> 31) ? 0xffffffffu : 0x80000000u;
                            unsigned long long k = ((unsigned long long)uv << 32)
                                                 | (unsigned)(LL - 1 - (base + i));
                            if (k > s0)      { s2 = s1; s1 = s0; s0 = k; }
                            else if (k > s1) { s2 = s1; s1 = k; }
                            else if (k > s2) { s2 = k; }
                        }
                    }
                }
                __syncwarp();
            }
            if (lane2 == 0) {
                g_cnt1[bh] = 0;
                __threadfence();
                atomicExch(&g_topdone[bh], 1);   // release
            }
        }
        return;
    }

    // ======================= ATTN ROLE (R15/R16-proven) =======================
    int bid2 = blockIdx.x - NSAMPBLK;
    int bh = bid2 / NSPLIT, split = bid2 % NSPLIT;
    int b = bh >> 3, h = bh & 7;
    int t = threadIdx.x;

    float* Qs = smem;                  // 2560
    float* KV = Qs + NT * DD;          // 8448
    float* Ss = KV + 64 * KTPAD;       // 5120

    int key0 = split * CHUNK;
    for (int i = t; i < CHUNK * DD; i += 256) {
        int j = i >> 6, d = i & 63;
        KV[d * KTPAD + j] = K[(((size_t)(b * LL + key0 + j) * HH + h) << 6) + d];
    }

    if (t == 0) {
        while (*(volatile int*)&g_topdone[bh] == 0) { }
        s_last = 0;
    }
    __syncthreads();
    __threadfence();

    for (int i = t; i < NT * 16; i += 256) {
        int u = i >> 4, c = i & 15;
        int ql = g_top[bh * NT + u];
        ((float4*)Qs)[i] =
            ((const float4*)Q)[(((size_t)(b * LL + ql) * HH + h) << 4) + c];
    }
    __syncthreads();

    // ---- phase 1: scores via FFMA2 ----
    {
        int ublk = t >> 5;
        int jg   = t & 31;
        unsigned long long acc[5][2];
#pragma unroll
        for (int k = 0; k < 5; k++) { acc[k][0] = 0ull; acc[k][1] = 0ull; }
        const ulonglong2* Kt2 = (const ulonglong2*)KV;
        const float4* Qs4 = (const float4*)Qs;
#pragma unroll 4
        for (int c = 0; c < 16; c++) {
            ulonglong2 kk0 = Kt2[(4 * c + 0) * 33 + jg];
            ulonglong2 kk1 = Kt2[(4 * c + 1) * 33 + jg];
            ulonglong2 kk2 = Kt2[(4 * c + 2) * 33 + jg];
            ulonglong2 kk3 = Kt2[(4 * c + 3) * 33 + jg];
#pragma unroll
            for (int k = 0; k < 5; k++) {
                float4 q = Qs4[(ublk * 5 + k) * 16 + c];
                unsigned long long qx = pk2(q.x, q.x);
                unsigned long long qy = pk2(q.y, q.y);
                unsigned long long qz = pk2(q.z, q.z);
                unsigned long long qw = pk2(q.w, q.w);
                acc[k][0] = ffma2(qx, kk0.x, acc[k][0]);
                acc[k][1] = ffma2(qx, kk0.y, acc[k][1]);
                acc[k][0] = ffma2(qy, kk1.x, acc[k][0]);
                acc[k][1] = ffma2(qy, kk1.y, acc[k][1]);
                acc[k][0] = ffma2(qz, kk2.x, acc[k][0]);
                acc[k][1] = ffma2(qz, kk2.y, acc[k][1]);
                acc[k][0] = ffma2(qw, kk3.x, acc[k][0]);
                acc[k][1] = ffma2(qw, kk3.y, acc[k][1]);
            }
        }
#pragma unroll
        for (int k = 0; k < 5; k++) {
            int u = ublk * 5 + k;
            float4 sv;
            upk2(acc[k][0], sv.x, sv.y);
            upk2(acc[k][1], sv.z, sv.w);
            sv.x *= SCALE; sv.y *= SCALE; sv.z *= SCALE; sv.w *= SCALE;
            *(float4*)(Ss + u * CHUNK + (jg << 2)) = sv;
        }
    }
    __syncwarp();

    // ---- phase 1.5: partial softmax ----
    {
        int w = t >> 5, lane = t & 31;
        for (int r = w * 5; r < w * 5 + 5; r++) {
            float v0 = Ss[r * CHUNK + lane];
            float v1 = Ss[r * CHUNK + lane + 32];
            float v2 = Ss[r * CHUNK + lane + 64];
            float v3 = Ss[r * CHUNK + lane + 96];
            float m = fmaxf(fmaxf(v0, v1), fmaxf(v2, v3));
#pragma unroll
            for (int o = 16; o; o >>= 1) m = fmaxf(m, __shfl_xor_sync(0xffffffffu, m, o));
            float e0 = __expf(v0 - m), e1 = __expf(v1 - m);
            float e2 = __expf(v2 - m), e3 = __expf(v3 - m);
            Ss[r * CHUNK + lane]      = e0;
            Ss[r * CHUNK + lane + 32] = e1;
            Ss[r * CHUNK + lane + 64] = e2;
            Ss[r * CHUNK + lane + 96] = e3;
            float s = e0 + e1 + e2 + e3;
#pragma unroll
            for (int o = 16; o; o >>= 1) s += __shfl_xor_sync(0xffffffffu, s, o);
            if (lane == 0) {
                g_pm[(bh * NSPLIT + split) * NT + r] = m;
                g_pl[(bh * NSPLIT + split) * NT + r] = s;
            }
        }
    }
    __syncthreads();

    // ---- deferred V staging ----
    for (int i = t; i < CHUNK * 16; i += 256) {
        int j = i >> 4, c = i & 15;
        ((float4*)KV)[i] =
            ((const float4*)V)[(((size_t)(b * LL + key0 + j) * HH + h) << 4) + c];
    }
    __syncthreads();

    // ---- phase 2: O = P @ V via FFMA2 ----
    {
        int ublk = t >> 5;
        int d4   = t & 15;
        int jh   = (t >> 4) & 1;
        unsigned long long acc[5][2];
#pragma unroll
        for (int k = 0; k < 5; k++) { acc[k][0] = 0ull; acc[k][1] = 0ull; }
        const ulonglong2* Vs2 = (const ulonglong2*)KV;
        int j0 = jh * 64;
#pragma unroll 4
        for (int jj = 0; jj < 64; jj += 4) {
            int j = j0 + jj;
            ulonglong2 vv0 = Vs2[(j + 0) * 16 + d4];
            ulonglong2 vv1 = Vs2[(j + 1) * 16 + d4];
            ulonglong2 vv2 = Vs2[(j + 2) * 16 + d4];
            ulonglong2 vv3 = Vs2[(j + 3) * 16 + d4];
#pragma unroll
            for (int k = 0; k < 5; k++) {
                float4 p = *(const float4*)(Ss + (ublk * 5 + k) * CHUNK + j);
                unsigned long long p0 = pk2(p.x, p.x);
                unsigned long long p1 = pk2(p.y, p.y);
                unsigned long long p2 = pk2(p.z, p.z);
                unsigned long long p3 = pk2(p.w, p.w);
                acc[k][0] = ffma2(p0, vv0.x, acc[k][0]);
                acc[k][1] = ffma2(p0, vv0.y, acc[k][1]);
                acc[k][0] = ffma2(p1, vv1.x, acc[k][0]);
                acc[k][1] = ffma2(p1, vv1.y, acc[k][1]);
                acc[k][0] = ffma2(p2, vv2.x, acc[k][0]);
                acc[k][1] = ffma2(p2, vv2.y, acc[k][1]);
                acc[k][0] = ffma2(p3, vv3.x, acc[k][0]);
                acc[k][1] = ffma2(p3, vv3.y, acc[k][1]);
            }
        }
        __syncthreads();
#pragma unroll
        for (int k = 0; k < 5; k++) {
            int u = ublk * 5 + k;
            ulonglong2 ov;
            ov.x = acc[k][0];
            ov.y = acc[k][1];
            *(ulonglong2*)(Ss + (jh * NT + u) * 64 + (d4 << 2)) = ov;
        }
    }
    __syncthreads();

    {
        const float4* Ss4 = (const float4*)Ss;
        float4* po4 = (float4*)(g_po + (size_t)(bh * NSPLIT + split) * NT * DD);
        for (int i = t; i < NT * 16; i += 256) {
            float4 a = Ss4[i];
            float4 c = Ss4[NT * 16 + i];
            a.x += c.x; a.y += c.y; a.z += c.z; a.w += c.w;
            po4[i] = a;
        }
    }

    // ---- fused combine: last split-block of this bh ----
    __syncthreads();
    __threadfence();
    if (t == 0)
        s_last = (atomicAdd(&g_cnt2[bh], 1) == NSPLIT - 1) ? 1 : 0;
    __syncthreads();
    if (!s_last) return;

    float* sw = smem;
    float* sl = smem + 640;
    if (t < NT) {
        float m = -3e38f;
#pragma unroll
        for (int s = 0; s < NSPLIT; s++)
            m = fmaxf(m, g_pm[(bh * NSPLIT + s) * NT + t]);
        float Ls = 0.f;
#pragma unroll
        for (int s = 0; s < NSPLIT; s++) {
            float w = __expf(g_pm[(bh * NSPLIT + s) * NT + t] - m);
            sw[t * NSPLIT + s] = w;
            Ls += g_pl[(bh * NSPLIT + s) * NT + t] * w;
        }
        sl[t] = Ls;
    }
    __syncthreads();
    for (int i = t; i < NT * DD; i += 256) {
        int u = i >> 6, d = i & 63;
        float acc = 0.f;
#pragma unroll
        for (int s = 0; s < NSPLIT; s++)
            acc += sw[u * NSPLIT + s] *
                   g_po[(size_t)(bh * NSPLIT + s) * NT * DD + i];
        out[(((size_t)(b * NT + u) * HH + h) << 6) + d] = acc / sl[u];
    }
    __syncthreads();
    if (t == 0) {
        g_cnt2[bh] = 0;
        g_topdone[bh] = 0;
    }
}

// ---------------- launcher: 1 kernel ----------------
extern "C" void kernel_launch(void* const* d_in, const int* in_sizes, int n_in,
                              void* d_out, int out_size) {
    const float* Q   = (const float*)d_in[0];
    const float* K   = (const float*)d_in[1];
    const float* V   = (const float*)d_in[2];
    const void*  idx = d_in[3];

    size_t smemD = (size_t)(NT * DD + 64 * KTPAD + NT * CHUNK) * sizeof(float); // 64512
    cudaFuncSetAttribute(fused_kernel, cudaFuncAttributeMaxDynamicSharedMemorySize, (int)smemD);
    fused_kernel<<<NSAMPBLK + NATTNBLK, 256, smemD>>>(Q, K, V, idx, (float*)d_out);
}